// round 1
// baseline (speedup 1.0000x reference)
#include <cuda_runtime.h>
#include <cstdint>

#define BB 1024
#define TT 128
#define DD 13
#define HH 512
#define CC 9
#define BT (BB*TT)
#define EPSF 1e-5f
#define NSTATBLK 256

// ---------------- scratch (device globals; allocation-free rule) ----------------
__device__ float g_xn[BT*16];        // LN'd input, padded D->16
__device__ float g_xK[BT*HH];        // per-layer xK projection
__device__ float g_z [BT*HH];        // per-layer z projection (tanh'd)
__device__ float g_o [BT*HH];        // recurrence output (pre-BN)
__device__ float g_psum[NSTATBLK*HH];
__device__ float g_psq [NSTATBLK*HH];
__device__ float g_mean[HH];
__device__ float g_rstd[HH];
__device__ float g_Wk[HH*HH];        // BN-folded WxK2
__device__ float g_Wz[HH*HH];        // BN-folded Wxz2
__device__ float g_bk[HH];
__device__ float g_bz[HH];

// ---------------- packed fp32x2 helpers (Blackwell FFMA2) ----------------
__device__ __forceinline__ unsigned long long pk2(float x, float y){
    unsigned long long r; asm("mov.b64 %0,{%1,%2};" : "=l"(r) : "f"(x), "f"(y)); return r;
}
__device__ __forceinline__ float2 upk2(unsigned long long v){
    float2 f; asm("mov.b64 {%0,%1},%2;" : "=f"(f.x), "=f"(f.y) : "l"(v)); return f;
}
__device__ __forceinline__ void fma2(unsigned long long &d, unsigned long long a, unsigned long long b){
    asm("fma.rn.f32x2 %0,%1,%2,%0;" : "+l"(d) : "l"(a), "l"(b));
}

// ---------------- 1) input LayerNorm over D=13 ----------------
__global__ void k_ln(const float* __restrict__ x, const float* __restrict__ g,
                     const float* __restrict__ b){
    int m = blockIdx.x*blockDim.x + threadIdx.x;
    if (m >= BT) return;
    const float* r = x + m*DD;
    float s = 0.f;
    #pragma unroll
    for (int k=0;k<DD;k++) s += r[k];
    float mu = s * (1.f/DD);
    float v = 0.f;
    #pragma unroll
    for (int k=0;k<DD;k++){ float d = r[k]-mu; v += d*d; }
    float rs = rsqrtf(v*(1.f/DD) + EPSF);
    float* o = g_xn + m*16;
    #pragma unroll
    for (int k=0;k<DD;k++) o[k] = (r[k]-mu)*rs*g[k] + b[k];
    o[13]=0.f; o[14]=0.f; o[15]=0.f;
}

// ---------------- 2) layer-1 projections (K=13, trivial) ----------------
__global__ void k_proj1(const float* __restrict__ WK, const float* __restrict__ bK,
                        const float* __restrict__ WZ, const float* __restrict__ bZ){
    int idx = blockIdx.x*blockDim.x + threadIdx.x;   // BT*HH threads
    int m = idx >> 9, j = idx & (HH-1);
    const float* xr = g_xn + m*16;
    const float* wk = WK + j*DD;
    const float* wz = WZ + j*DD;
    float ak = bK[j], az = bZ[j];
    #pragma unroll
    for (int k=0;k<DD;k++){ float xv = xr[k]; ak = fmaf(xv, wk[k], ak); az = fmaf(xv, wz[k], az); }
    g_xK[idx] = ak;
    g_z[idx]  = tanhf(az);
}

// ---------------- 3) recurrence: 8 batch rows per CTA, h in SMEM ----------------
__global__ void __launch_bounds__(512) k_recur(const float* __restrict__ W,
                                               const float* __restrict__ bh){
    __shared__ __align__(16) float hs[8][HH];
    int tid = threadIdx.x;
    int b0  = blockIdx.x*8;
    #pragma unroll
    for (int r=0;r<8;r++) hs[r][tid] = 0.f;
    float bj = bh[tid];
    const float4* __restrict__ Wr = (const float4*)(W + tid*HH);
    __syncthreads();

    for (int t=0;t<TT;t++){
        unsigned long long acc[8];
        #pragma unroll
        for (int r=0;r<8;r++) acc[r] = pk2(0.f,0.f);
        #pragma unroll 4
        for (int k4=0;k4<HH/4;k4++){
            float4 w = Wr[k4];
            unsigned long long wlo = pk2(w.x,w.y), whi = pk2(w.z,w.w);
            #pragma unroll
            for (int r=0;r<8;r++){
                float4 h4 = *(const float4*)&hs[r][k4*4];
                fma2(acc[r], pk2(h4.x,h4.y), wlo);
                fma2(acc[r], pk2(h4.z,h4.w), whi);
            }
        }
        float nh[8];
        #pragma unroll
        for (int r=0;r<8;r++){
            float2 a = upk2(acc[r]);
            int off = ((b0+r)*TT + t)*HH + tid;
            float gk = g_xK[off];
            float zt = g_z[off];
            float K  = 1.f/(1.f + expf(-(gk + a.x + a.y + bj)));
            float hp = hs[r][tid];
            nh[r] = tanhf(K*hp + (1.f-K)*zt);
        }
        __syncthreads();
        #pragma unroll
        for (int r=0;r<8;r++){
            hs[r][tid] = nh[r];
            g_o[((b0+r)*TT + t)*HH + tid] = nh[r];
        }
        __syncthreads();
    }
}

// ---------------- 4) BN stats: deterministic 2-stage column reduce ----------------
__global__ void k_stats(){
    int tid = threadIdx.x;
    int m0  = blockIdx.x*512;
    const float* o = g_o + (size_t)m0*HH;
    float s = 0.f, q = 0.f;
    for (int i=0;i<512;i++){ float v = o[i*HH + tid]; s += v; q = fmaf(v, v, q); }
    g_psum[blockIdx.x*HH + tid] = s;
    g_psq [blockIdx.x*HH + tid] = q;
}
__global__ void k_statsfin(){
    int t = threadIdx.x;
    float s = 0.f, q = 0.f;
    for (int i=0;i<NSTATBLK;i++){ s += g_psum[i*HH + t]; q += g_psq[i*HH + t]; }
    float m = s * (1.f/BT);
    float v = q * (1.f/BT) - m*m;
    g_mean[t] = m;
    g_rstd[t] = rsqrtf(v + EPSF);
}

// ---------------- 5) fold BN into projection weights ----------------
__global__ void __launch_bounds__(512) k_fold(const float* __restrict__ WK, const float* __restrict__ bKb,
                                              const float* __restrict__ WZ, const float* __restrict__ bZb,
                                              const float* __restrict__ bng, const float* __restrict__ bnb){
    __shared__ float rk[16], rz[16];
    int j = blockIdx.x, tid = threadIdx.x;
    float s = bng[tid]*g_rstd[tid];
    float c = bnb[tid] - g_mean[tid]*s;
    float wk = WK[j*HH+tid], wz = WZ[j*HH+tid];
    g_Wk[j*HH+tid] = wk*s;
    g_Wz[j*HH+tid] = wz*s;
    float pk = wk*c, pz = wz*c;
    #pragma unroll
    for (int o=16;o;o>>=1){ pk += __shfl_xor_sync(~0u,pk,o); pz += __shfl_xor_sync(~0u,pz,o); }
    if ((tid&31)==0){ rk[tid>>5]=pk; rz[tid>>5]=pz; }
    __syncthreads();
    if (tid==0){
        float a=0.f, bq=0.f;
        #pragma unroll
        for (int i=0;i<16;i++){ a+=rk[i]; bq+=rz[i]; }
        g_bk[j] = bKb[j] + a;
        g_bz[j] = bZb[j] + bq;
    }
}

// ---------------- 6) layer-2/3 projections: 32-row tiles, fp32x2 ----------------
__global__ void __launch_bounds__(512) k_proj2(){
    extern __shared__ __align__(16) float xs[];   // 32 x 512 floats = 64 KB
    int tid = threadIdx.x;
    int m0  = blockIdx.x*32;
    const float4* __restrict__ src = (const float4*)(g_o + (size_t)m0*HH);
    float4* dst4 = (float4*)xs;
    #pragma unroll
    for (int i=0;i<8;i++) dst4[tid + i*512] = src[tid + i*512];
    __syncthreads();

    // pass 1: xK = in @ Wk' + bk'
    {
        unsigned long long acc[32];
        #pragma unroll
        for (int r=0;r<32;r++) acc[r] = pk2(0.f,0.f);
        const float4* __restrict__ Wr = (const float4*)(g_Wk + tid*HH);
        #pragma unroll 2
        for (int k4=0;k4<HH/4;k4++){
            float4 w = Wr[k4];
            unsigned long long wlo = pk2(w.x,w.y), whi = pk2(w.z,w.w);
            #pragma unroll
            for (int r=0;r<32;r++){
                float4 h4 = *(const float4*)&xs[r*HH + k4*4];
                fma2(acc[r], pk2(h4.x,h4.y), wlo);
                fma2(acc[r], pk2(h4.z,h4.w), whi);
            }
        }
        float bb = g_bk[tid];
        #pragma unroll
        for (int r=0;r<32;r++){
            float2 a = upk2(acc[r]);
            g_xK[(m0+r)*HH + tid] = a.x + a.y + bb;
        }
    }
    // pass 2: z = tanh(in @ Wz' + bz')
    {
        unsigned long long acc[32];
        #pragma unroll
        for (int r=0;r<32;r++) acc[r] = pk2(0.f,0.f);
        const float4* __restrict__ Wr = (const float4*)(g_Wz + tid*HH);
        #pragma unroll 2
        for (int k4=0;k4<HH/4;k4++){
            float4 w = Wr[k4];
            unsigned long long wlo = pk2(w.x,w.y), whi = pk2(w.z,w.w);
            #pragma unroll
            for (int r=0;r<32;r++){
                float4 h4 = *(const float4*)&xs[r*HH + k4*4];
                fma2(acc[r], pk2(h4.x,h4.y), wlo);
                fma2(acc[r], pk2(h4.z,h4.w), whi);
            }
        }
        float bb = g_bz[tid];
        #pragma unroll
        for (int r=0;r<32;r++){
            float2 a = upk2(acc[r]);
            g_z[(m0+r)*HH + tid] = tanhf(a.x + a.y + bb);
        }
    }
}

// ---------------- 7) head: BN + LN(last step) + logits + log_softmax ----------------
__global__ void __launch_bounds__(512) k_head(const float* __restrict__ bng, const float* __restrict__ bnb,
                                              const float* __restrict__ lng, const float* __restrict__ lnb,
                                              const float* __restrict__ Wc,  const float* __restrict__ bc,
                                              float* __restrict__ out){
    __shared__ float red[16];
    __shared__ float hsm[HH];
    __shared__ float lg[CC];
    int b = blockIdx.x, tid = threadIdx.x;

    float v = g_o[(b*TT + TT-1)*HH + tid];
    float y = (v - g_mean[tid])*g_rstd[tid]*bng[tid] + bnb[tid];

    float t1 = y;
    #pragma unroll
    for (int o=16;o;o>>=1) t1 += __shfl_xor_sync(~0u,t1,o);
    if ((tid&31)==0) red[tid>>5] = t1;
    __syncthreads();
    float mu = 0.f;
    #pragma unroll
    for (int i=0;i<16;i++) mu += red[i];
    mu *= (1.f/HH);
    __syncthreads();

    float d = y - mu;
    float t2 = d*d;
    #pragma unroll
    for (int o=16;o;o>>=1) t2 += __shfl_xor_sync(~0u,t2,o);
    if ((tid&31)==0) red[tid>>5] = t2;
    __syncthreads();
    float var = 0.f;
    #pragma unroll
    for (int i=0;i<16;i++) var += red[i];
    var *= (1.f/HH);
    float rs = rsqrtf(var + EPSF);
    hsm[tid] = d*rs*lng[tid] + lnb[tid];
    __syncthreads();

    int w = tid>>5, l = tid&31;
    if (w < CC){
        float p = 0.f;
        for (int k=l;k<HH;k+=32) p = fmaf(hsm[k], Wc[w*HH + k], p);
        #pragma unroll
        for (int o=16;o;o>>=1) p += __shfl_xor_sync(~0u,p,o);
        if (l==0) lg[w] = p + bc[w];
    }
    __syncthreads();
    if (tid==0){
        float mx = lg[0];
        #pragma unroll
        for (int c=1;c<CC;c++) mx = fmaxf(mx, lg[c]);
        float sm = 0.f;
        #pragma unroll
        for (int c=0;c<CC;c++) sm += expf(lg[c]-mx);
        float lse = mx + logf(sm);
        #pragma unroll
        for (int c=0;c<CC;c++) out[b*CC + c] = lg[c] - lse;
    }
}

// ---------------- launch sequence ----------------
extern "C" void kernel_launch(void* const* d_in, const int* in_sizes, int n_in,
                              void* d_out, int out_size){
    const float* x      = (const float*)d_in[0];
    const float* inln_g = (const float*)d_in[1];
    const float* inln_b = (const float*)d_in[2];
    const float* WxK1   = (const float*)d_in[3];
    const float* bxK1   = (const float*)d_in[4];
    const float* Wxz1   = (const float*)d_in[5];
    const float* bxz1   = (const float*)d_in[6];
    const float* WhK1   = (const float*)d_in[7];
    const float* bhK1   = (const float*)d_in[8];
    const float* bn1_g  = (const float*)d_in[9];
    const float* bn1_b  = (const float*)d_in[10];
    const float* WxK2   = (const float*)d_in[11];
    const float* bxK2   = (const float*)d_in[12];
    const float* Wxz2   = (const float*)d_in[13];
    const float* bxz2   = (const float*)d_in[14];
    const float* WhK2   = (const float*)d_in[15];
    const float* bhK2   = (const float*)d_in[16];
    const float* bn2_g  = (const float*)d_in[17];
    const float* bn2_b  = (const float*)d_in[18];
    const float* cln_g  = (const float*)d_in[19];
    const float* cln_b  = (const float*)d_in[20];
    const float* Wc     = (const float*)d_in[21];
    const float* bc     = (const float*)d_in[22];
    float* out = (float*)d_out;

    cudaFuncSetAttribute(k_proj2, cudaFuncAttributeMaxDynamicSharedMemorySize, 32*HH*4);

    // input LN + layer-1 projections
    k_ln   <<<BT/256, 256>>>(x, inln_g, inln_b);
    k_proj1<<<(BT*HH)/512, 512>>>(WxK1, bxK1, Wxz1, bxz1);

    // layer 1
    k_recur<<<BB/8, 512>>>(WhK1, bhK1);
    k_stats<<<NSTATBLK, 512>>>();
    k_statsfin<<<1, 512>>>();
    k_fold <<<HH, 512>>>(WxK2, bxK2, Wxz2, bxz2, bn1_g, bn1_b);

    // layer 2
    k_proj2<<<BT/32, 512, 32*HH*4>>>();
    k_recur<<<BB/8, 512>>>(WhK2, bhK2);
    k_stats<<<NSTATBLK, 512>>>();
    k_statsfin<<<1, 512>>>();
    k_fold <<<HH, 512>>>(WxK2, bxK2, Wxz2, bxz2, bn2_g, bn2_b);

    // layer 3 (shared weights with layer 2)
    k_proj2<<<BT/32, 512, 32*HH*4>>>();
    k_recur<<<BB/8, 512>>>(WhK2, bhK2);
    k_stats<<<NSTATBLK, 512>>>();
    k_statsfin<<<1, 512>>>();

    // head
    k_head <<<BB, 512>>>(bn2_g, bn2_b, cln_g, cln_b, Wc, bc, out);
}

// round 2
// speedup vs baseline: 2.1259x; 2.1259x over previous
#include <cuda_runtime.h>
#include <cstdint>

typedef unsigned long long ull;

#define BB 1024
#define TT 128
#define DD 13
#define HH 512
#define CC 9
#define BT (BB*TT)
#define EPSF 1e-5f
#define NRB 128            // recurrence CTAs == stats partials

// ---------------- scratch (device globals) ----------------
__device__ float g_xn[BT*16];
__device__ float g_xK[BT*HH];
__device__ float g_z [BT*HH];
__device__ float g_o [BT*HH];
__device__ float g_psum[NRB*HH];
__device__ float g_psq [NRB*HH];
__device__ float g_mean[HH], g_rstd[HH], g_s[HH], g_c[HH];
__device__ ull   g_Wp [256*HH];     // packed-transposed recurrence W
__device__ ull   g_Wkp[256*HH];     // packed-transposed BN-folded WxK2
__device__ ull   g_Wzp[256*HH];     // packed-transposed BN-folded Wxz2
__device__ float g_bk[HH], g_bz[HH];

// ---------------- helpers ----------------
__device__ __forceinline__ ull pk2(float x, float y){
    ull r; asm("mov.b64 %0,{%1,%2};" : "=l"(r) : "f"(x), "f"(y)); return r;
}
__device__ __forceinline__ float2 upk2(ull v){
    float2 f; asm("mov.b64 {%0,%1},%2;" : "=f"(f.x), "=f"(f.y) : "l"(v)); return f;
}
__device__ __forceinline__ void fma2(ull &d, ull a, ull b){
    asm("fma.rn.f32x2 %0,%1,%2,%0;" : "+l"(d) : "l"(a), "l"(b));
}
// ld.shared.v2.u64: two packed fp32 pairs, no mov packing
__device__ __forceinline__ void lds2(ull &a, ull &b, const float* p){
    unsigned sa = (unsigned)__cvta_generic_to_shared(p);
    asm volatile("ld.shared.v2.u64 {%0,%1},[%2];" : "=l"(a), "=l"(b) : "r"(sa));
}
__device__ __forceinline__ float sigm_f(float x){
    return __fdividef(1.f, 1.f + __expf(-x));
}
__device__ __forceinline__ float tanh_f(float x){
    return 1.f - 2.f*__fdividef(1.f, __expf(2.f*x) + 1.f);
}

// ---------------- 1) input LayerNorm over D=13 ----------------
__global__ void k_ln(const float* __restrict__ x, const float* __restrict__ g,
                     const float* __restrict__ b){
    int m = blockIdx.x*blockDim.x + threadIdx.x;
    if (m >= BT) return;
    const float* r = x + m*DD;
    float s = 0.f;
    #pragma unroll
    for (int k=0;k<DD;k++) s += r[k];
    float mu = s * (1.f/DD);
    float v = 0.f;
    #pragma unroll
    for (int k=0;k<DD;k++){ float d = r[k]-mu; v += d*d; }
    float rs = rsqrtf(v*(1.f/DD) + EPSF);
    float* o = g_xn + m*16;
    #pragma unroll
    for (int k=0;k<DD;k++) o[k] = (r[k]-mu)*rs*g[k] + b[k];
    o[13]=0.f; o[14]=0.f; o[15]=0.f;
}

// ---------------- 2) layer-1 projections (K=13), W in registers ----------------
__global__ void __launch_bounds__(512) k_proj1(const float* __restrict__ WK, const float* __restrict__ bK,
                                               const float* __restrict__ WZ, const float* __restrict__ bZ){
    __shared__ float xt[64][16];
    int tid = threadIdx.x;
    int m0  = blockIdx.x*64;
    #pragma unroll
    for (int i=0;i<2;i++){
        int idx = tid + i*512;
        xt[idx>>4][idx&15] = g_xn[m0*16 + idx];
    }
    float wk[DD], wz[DD];
    #pragma unroll
    for (int i=0;i<DD;i++){ wk[i]=WK[tid*DD+i]; wz[i]=WZ[tid*DD+i]; }
    float bk = bK[tid], bz = bZ[tid];
    __syncthreads();
    for (int m=0;m<64;m++){
        float ak = bk, az = bz;
        #pragma unroll
        for (int i=0;i<DD;i++){ float xv = xt[m][i]; ak = fmaf(xv,wk[i],ak); az = fmaf(xv,wz[i],az); }
        g_xK[(m0+m)*HH + tid] = ak;
        g_z [(m0+m)*HH + tid] = tanh_f(az);
    }
}

// ---------------- 3) pack W: [j][k] -> pair-packed transposed [k/2][j] ----------------
// sel: 0->g_Wp, 1->g_Wkp, 2->g_Wzp ; scaled: multiply by g_s[k] (BN fold)
__global__ void k_pack(const float* __restrict__ src, int sel, int scaled){
    __shared__ float ts[32][65];
    ull* dst = (sel==0) ? g_Wp : ((sel==1) ? g_Wkp : g_Wzp);
    int t  = threadIdx.x;            // 256 threads
    int j0 = blockIdx.x*32;
    int k0 = blockIdx.y*64;
    #pragma unroll
    for (int it=0; it<8; it++){
        int idx = it*256 + t;
        int jj = idx >> 6, kk = idx & 63;
        float v = src[(j0+jj)*HH + k0 + kk];
        if (scaled) v *= g_s[k0+kk];
        ts[jj][kk] = v;
    }
    __syncthreads();
    #pragma unroll
    for (int it=0; it<4; it++){
        int idx = it*256 + t;
        int jj = idx & 31, kpl = idx >> 5;   // kpl 0..31
        dst[(k0/2 + kpl)*HH + j0 + jj] = pk2(ts[jj][2*kpl], ts[jj][2*kpl+1]);
    }
}

// ---------------- 4) recurrence (+ fused BN partial stats) ----------------
__global__ void __launch_bounds__(512,1) k_recur(const float* __restrict__ bh){
    __shared__ __align__(16) float hs[8][HH];
    int tid = threadIdx.x;
    int b0  = blockIdx.x*8;
    #pragma unroll
    for (int r=0;r<8;r++) hs[r][tid] = 0.f;
    float bj = bh[tid];
    float ss = 0.f, sq = 0.f;
    __syncthreads();

    for (int t=0;t<TT;t++){
        float gk[8], zt[8];
        int off[8];
        #pragma unroll
        for (int r=0;r<8;r++){
            off[r] = ((b0+r)*TT + t)*HH + tid;
            gk[r] = g_xK[off[r]];
            zt[r] = g_z [off[r]];
        }
        ull acc[8];
        #pragma unroll
        for (int r=0;r<8;r++) acc[r] = 0ull;

        const ull* __restrict__ wp = g_Wp + tid;
        #pragma unroll 4
        for (int kp2=0; kp2<128; kp2++){
            ull w0 = __ldg(wp + (2*kp2  )*HH);
            ull w1 = __ldg(wp + (2*kp2+1)*HH);
            #pragma unroll
            for (int r=0;r<8;r++){
                ull h0,h1;
                lds2(h0,h1,&hs[r][4*kp2]);
                fma2(acc[r],h0,w0);
                fma2(acc[r],h1,w1);
            }
        }
        float nh[8];
        #pragma unroll
        for (int r=0;r<8;r++){
            float2 a = upk2(acc[r]);
            float K  = sigm_f(gk[r] + a.x + a.y + bj);
            nh[r] = tanh_f(K*hs[r][tid] + (1.f-K)*zt[r]);
        }
        __syncthreads();
        #pragma unroll
        for (int r=0;r<8;r++){
            hs[r][tid] = nh[r];
            g_o[off[r]] = nh[r];
            ss += nh[r];
            sq  = fmaf(nh[r], nh[r], sq);
        }
        __syncthreads();
    }
    g_psum[blockIdx.x*HH + tid] = ss;
    g_psq [blockIdx.x*HH + tid] = sq;
}

// ---------------- 5) finalize BN stats + fold vectors ----------------
__global__ void k_statsfin(const float* __restrict__ bng, const float* __restrict__ bnb){
    int t = threadIdx.x;
    float s = 0.f, q = 0.f;
    for (int i=0;i<NRB;i++){ s += g_psum[i*HH + t]; q += g_psq[i*HH + t]; }
    float m  = s * (1.f/BT);
    float v  = q * (1.f/BT) - m*m;
    float rs = rsqrtf(v + EPSF);
    g_mean[t] = m;
    g_rstd[t] = rs;
    float sc = bng[t]*rs;
    g_s[t] = sc;
    g_c[t] = bnb[t] - m*sc;
}

// ---------------- 6) folded biases: b' = b + W @ c ----------------
__global__ void k_bias(const float* __restrict__ WK, const float* __restrict__ bK,
                       const float* __restrict__ WZ, const float* __restrict__ bZ){
    __shared__ float sk[8], sz[8];
    int j = blockIdx.x, t = threadIdx.x;     // 256 threads
    float ck = 0.f, cz = 0.f;
    for (int k=t;k<HH;k+=256){
        float c = g_c[k];
        ck = fmaf(WK[j*HH+k], c, ck);
        cz = fmaf(WZ[j*HH+k], c, cz);
    }
    #pragma unroll
    for (int o=16;o;o>>=1){ ck += __shfl_xor_sync(~0u,ck,o); cz += __shfl_xor_sync(~0u,cz,o); }
    if ((t&31)==0){ sk[t>>5]=ck; sz[t>>5]=cz; }
    __syncthreads();
    if (t==0){
        float a=0.f,b2=0.f;
        #pragma unroll
        for (int i=0;i<8;i++){ a+=sk[i]; b2+=sz[i]; }
        g_bk[j] = bK[j] + a;
        g_bz[j] = bZ[j] + b2;
    }
}

// ---------------- 7) fused layer-2/3 projections (BN folded) ----------------
__global__ void __launch_bounds__(512,1) k_proj2(){
    __shared__ __align__(16) float xs[16*HH];   // 32 KB
    int tid = threadIdx.x;
    int m0  = blockIdx.x*16;
    const float4* __restrict__ src = (const float4*)(g_o + (size_t)m0*HH);
    float4* d4 = (float4*)xs;
    #pragma unroll
    for (int i=0;i<4;i++) d4[tid + i*512] = src[tid + i*512];
    __syncthreads();

    ull aK[16], aZ[16];
    #pragma unroll
    for (int r=0;r<16;r++){ aK[r]=0ull; aZ[r]=0ull; }

    const ull* __restrict__ wkp = g_Wkp + tid;
    const ull* __restrict__ wzp = g_Wzp + tid;
    #pragma unroll 2
    for (int kp2=0; kp2<128; kp2++){
        ull k0 = __ldg(wkp + (2*kp2  )*HH);
        ull k1 = __ldg(wkp + (2*kp2+1)*HH);
        ull z0 = __ldg(wzp + (2*kp2  )*HH);
        ull z1 = __ldg(wzp + (2*kp2+1)*HH);
        #pragma unroll
        for (int r=0;r<16;r++){
            ull h0,h1;
            lds2(h0,h1,&xs[r*HH + 4*kp2]);
            fma2(aK[r],h0,k0); fma2(aK[r],h1,k1);
            fma2(aZ[r],h0,z0); fma2(aZ[r],h1,z1);
        }
    }
    float bk = g_bk[tid], bz = g_bz[tid];
    #pragma unroll
    for (int r=0;r<16;r++){
        float2 a = upk2(aK[r]);
        g_xK[(m0+r)*HH + tid] = a.x + a.y + bk;
        float2 c = upk2(aZ[r]);
        g_z [(m0+r)*HH + tid] = tanh_f(c.x + c.y + bz);
    }
}

// ---------------- 8) head: BN + LN(last step) + logits + log_softmax ----------------
__global__ void __launch_bounds__(512) k_head(const float* __restrict__ bng, const float* __restrict__ bnb,
                                              const float* __restrict__ lng, const float* __restrict__ lnb,
                                              const float* __restrict__ Wc,  const float* __restrict__ bc,
                                              float* __restrict__ out){
    __shared__ float red[16];
    __shared__ float hsm[HH];
    __shared__ float lg[CC];
    int b = blockIdx.x, tid = threadIdx.x;

    float v = g_o[(b*TT + TT-1)*HH + tid];
    float y = (v - g_mean[tid])*g_rstd[tid]*bng[tid] + bnb[tid];

    float t1 = y;
    #pragma unroll
    for (int o=16;o;o>>=1) t1 += __shfl_xor_sync(~0u,t1,o);
    if ((tid&31)==0) red[tid>>5] = t1;
    __syncthreads();
    float mu = 0.f;
    #pragma unroll
    for (int i=0;i<16;i++) mu += red[i];
    mu *= (1.f/HH);
    __syncthreads();

    float d = y - mu;
    float t2 = d*d;
    #pragma unroll
    for (int o=16;o;o>>=1) t2 += __shfl_xor_sync(~0u,t2,o);
    if ((tid&31)==0) red[tid>>5] = t2;
    __syncthreads();
    float var = 0.f;
    #pragma unroll
    for (int i=0;i<16;i++) var += red[i];
    var *= (1.f/HH);
    float rs = rsqrtf(var + EPSF);
    hsm[tid] = d*rs*lng[tid] + lnb[tid];
    __syncthreads();

    int w = tid>>5, l = tid&31;
    if (w < CC){
        float p = 0.f;
        for (int k=l;k<HH;k+=32) p = fmaf(hsm[k], Wc[w*HH + k], p);
        #pragma unroll
        for (int o=16;o;o>>=1) p += __shfl_xor_sync(~0u,p,o);
        if (l==0) lg[w] = p + bc[w];
    }
    __syncthreads();
    if (tid==0){
        float mx = lg[0];
        #pragma unroll
        for (int c=1;c<CC;c++) mx = fmaxf(mx, lg[c]);
        float sm = 0.f;
        #pragma unroll
        for (int c=0;c<CC;c++) sm += expf(lg[c]-mx);
        float lse = mx + logf(sm);
        #pragma unroll
        for (int c=0;c<CC;c++) out[b*CC + c] = lg[c] - lse;
    }
}

// ---------------- launch sequence ----------------
extern "C" void kernel_launch(void* const* d_in, const int* in_sizes, int n_in,
                              void* d_out, int out_size){
    const float* x      = (const float*)d_in[0];
    const float* inln_g = (const float*)d_in[1];
    const float* inln_b = (const float*)d_in[2];
    const float* WxK1   = (const float*)d_in[3];
    const float* bxK1   = (const float*)d_in[4];
    const float* Wxz1   = (const float*)d_in[5];
    const float* bxz1   = (const float*)d_in[6];
    const float* WhK1   = (const float*)d_in[7];
    const float* bhK1   = (const float*)d_in[8];
    const float* bn1_g  = (const float*)d_in[9];
    const float* bn1_b  = (const float*)d_in[10];
    const float* WxK2   = (const float*)d_in[11];
    const float* bxK2   = (const float*)d_in[12];
    const float* Wxz2   = (const float*)d_in[13];
    const float* bxz2   = (const float*)d_in[14];
    const float* WhK2   = (const float*)d_in[15];
    const float* bhK2   = (const float*)d_in[16];
    const float* bn2_g  = (const float*)d_in[17];
    const float* bn2_b  = (const float*)d_in[18];
    const float* cln_g  = (const float*)d_in[19];
    const float* cln_b  = (const float*)d_in[20];
    const float* Wc     = (const float*)d_in[21];
    const float* bc     = (const float*)d_in[22];
    float* out = (float*)d_out;

    dim3 pg(16,8);

    // input LN + layer-1 projections
    k_ln   <<<BT/256, 256>>>(x, inln_g, inln_b);
    k_proj1<<<BT/64, 512>>>(WxK1, bxK1, Wxz1, bxz1);

    // layer 1
    k_pack   <<<pg, 256>>>(WhK1, 0, 0);
    k_recur  <<<NRB, 512>>>(bhK1);
    k_statsfin<<<1, 512>>>(bn1_g, bn1_b);
    k_pack   <<<pg, 256>>>(WxK2, 1, 1);
    k_pack   <<<pg, 256>>>(Wxz2, 2, 1);
    k_bias   <<<HH, 256>>>(WxK2, bxK2, Wxz2, bxz2);

    // layer 2
    k_proj2  <<<BT/16, 512>>>();
    k_pack   <<<pg, 256>>>(WhK2, 0, 0);
    k_recur  <<<NRB, 512>>>(bhK2);
    k_statsfin<<<1, 512>>>(bn2_g, bn2_b);
    k_pack   <<<pg, 256>>>(WxK2, 1, 1);
    k_pack   <<<pg, 256>>>(Wxz2, 2, 1);
    k_bias   <<<HH, 256>>>(WxK2, bxK2, Wxz2, bxz2);

    // layer 3 (shared weights; g_Wp still holds packed WhK2)
    k_proj2  <<<BT/16, 512>>>();
    k_recur  <<<NRB, 512>>>(bhK2);
    k_statsfin<<<1, 512>>>(bn2_g, bn2_b);

    // head
    k_head <<<BB, 512>>>(bn2_g, bn2_b, cln_g, cln_b, Wc, bc, out);
}